// round 10
// baseline (speedup 1.0000x reference)
#include <cuda_runtime.h>
#include <math.h>
#include <stdint.h>

#define D 1024
#define NH 16
#define DH 64
#define BB 2
#define SS 2048
#define MTOK (BB*SS)       // 4096
#define NEGV -1000000000.0f

// ---------------- scratch (device globals; no allocations) ----------------
__device__ float g_xln[MTOK*D];
__device__ float g_q[MTOK*D];
__device__ float g_k[MTOK*D];
__device__ float g_v[MTOK*D];
__device__ float g_ao[MTOK*D];
__device__ float g_h[MTOK*D];
__device__ float g_hln[MTOK*D];
__device__ float g_r[MTOK*D];
__device__ float g_z[MTOK*D];
__device__ float g_mid[(size_t)MTOK*4*D];

__device__ __forceinline__ uint32_t f2tf(float x){
    uint32_t r; asm("cvt.rna.tf32.f32 %0, %1;" : "=r"(r) : "f"(x)); return r;
}
__device__ __forceinline__ uint32_t bits2tf(uint32_t b){
    uint32_t r; asm("cvt.rna.tf32.f32 %0, %1;" : "=r"(r) : "f"(__uint_as_float(b))); return r;
}
__device__ __forceinline__ void mma8(float* c, const uint32_t* a, uint32_t b0, uint32_t b1){
    asm volatile(
        "mma.sync.aligned.m16n8k8.row.col.f32.tf32.tf32.f32 "
        "{%0,%1,%2,%3}, {%4,%5,%6,%7}, {%8,%9}, {%0,%1,%2,%3};"
        : "+f"(c[0]), "+f"(c[1]), "+f"(c[2]), "+f"(c[3])
        : "r"(a[0]), "r"(a[1]), "r"(a[2]), "r"(a[3]), "r"(b0), "r"(b1));
}
__device__ __forceinline__ void cpa16(uint32_t s, const void* g){
    asm volatile("cp.async.cg.shared.global [%0], [%1], 16;" :: "r"(s), "l"(g));
}

// ---------------- fused embedding + LayerNorm1 ----------------
__global__ __launch_bounds__(256) void embed_ln_kernel(
    const int* __restrict__ tids, const float* __restrict__ tok,
    const float* __restrict__ pos, const float* __restrict__ gam,
    const float* __restrict__ bet, float* __restrict__ out)
{
    int row = blockIdx.x;
    int s   = row % SS;
    int t   = tids[row];
    const float* te = tok + (size_t)t * D;
    const float* pe = pos + (size_t)s * D;
    float v[4];
    float sum = 0.f, sq = 0.f;
#pragma unroll
    for (int i = 0; i < 4; i++) {
        int d = threadIdx.x + 256*i;
        float x = te[d] + pe[d];
        v[i] = x; sum += x; sq += x*x;
    }
    __shared__ float s1[256], s2[256];
    int tid = threadIdx.x;
    s1[tid] = sum; s2[tid] = sq; __syncthreads();
    for (int o = 128; o > 0; o >>= 1) {
        if (tid < o) { s1[tid] += s1[tid+o]; s2[tid] += s2[tid+o]; }
        __syncthreads();
    }
    float mu  = s1[0] * (1.f/D);
    float var = s2[0] * (1.f/D) - mu*mu;
    float rs  = rsqrtf(var + 1e-5f);
#pragma unroll
    for (int i = 0; i < 4; i++) {
        int d = threadIdx.x + 256*i;
        out[(size_t)row*D + d] = (v[i]-mu)*rs*gam[d] + bet[d];
    }
}

// ---------------- generic LayerNorm ----------------
__global__ __launch_bounds__(256) void ln_kernel(
    const float* __restrict__ X, const float* __restrict__ gam,
    const float* __restrict__ bet, float* __restrict__ out)
{
    int row = blockIdx.x;
    const float* x = X + (size_t)row*D;
    float v[4];
    float sum = 0.f, sq = 0.f;
#pragma unroll
    for (int i = 0; i < 4; i++) {
        int d = threadIdx.x + 256*i;
        float xx = x[d];
        v[i] = xx; sum += xx; sq += xx*xx;
    }
    __shared__ float s1[256], s2[256];
    int tid = threadIdx.x;
    s1[tid] = sum; s2[tid] = sq; __syncthreads();
    for (int o = 128; o > 0; o >>= 1) {
        if (tid < o) { s1[tid] += s1[tid+o]; s2[tid] += s2[tid+o]; }
        __syncthreads();
    }
    float mu  = s1[0] * (1.f/D);
    float var = s2[0] * (1.f/D) - mu*mu;
    float rs  = rsqrtf(var + 1e-5f);
#pragma unroll
    for (int i = 0; i < 4; i++) {
        int d = threadIdx.x + 256*i;
        out[(size_t)row*D + d] = (v[i]-mu)*rs*gam[d] + bet[d];
    }
}

// ---------------- tf32 tensor-core GEMM body, 3-stage cp.async --------------
// C[M,N] = A[M,K] @ B[K,N] + bias [, GELU] [, + res]
// 128x128 CTA tile, BK=16, 256 threads (8 warps 2x4), warp tile 64x32.
// Fragments converted to tf32 with round-to-nearest-even at LDS time.
#define A_PITCH 20
#define B_PITCH 136
#define A_STAGE (128*A_PITCH)            // 2560 u32
#define B_STAGE (16*B_PITCH)             // 2176 u32
#define GEMM_SMEM ((3*A_STAGE + 3*B_STAGE)*4)   // 56832 B

__device__ __forceinline__ void gemm_body(
    const float* __restrict__ A, const float* __restrict__ Bm,
    const float* __restrict__ bias, const float* __restrict__ res,
    float* __restrict__ C, int N, int K, int bx, int by,
    uint32_t* dyn, int GELU, int RES)
{
    uint32_t* smA = dyn;
    uint32_t* smB = dyn + 3*A_STAGE;

    const int tid  = threadIdx.x;
    const int lane = tid & 31;
    const int warp = tid >> 5;
    const int wm   = warp >> 2;
    const int wn   = warp & 3;
    const int bm   = by * 128;
    const int bn   = bx * 128;
    const int r0   = lane >> 2;
    const int c0   = lane & 3;

    const int ar = tid >> 2,  ac = (tid & 3) * 4;
    const int br = tid >> 5,  bc = (tid & 31) * 4;

    uint32_t saA = (uint32_t)__cvta_generic_to_shared(smA);
    uint32_t saB = (uint32_t)__cvta_generic_to_shared(smB);

#define ISSUE_TILE(stage, t) do{                                              \
    int k0_ = (t) << 4;                                                       \
    uint32_t sA_ = saA + (uint32_t)(stage)*A_STAGE*4;                         \
    cpa16(sA_ + (ar*A_PITCH + ac)*4,      A + (size_t)(bm+ar)*K + k0_ + ac);  \
    cpa16(sA_ + ((ar+64)*A_PITCH + ac)*4, A + (size_t)(bm+ar+64)*K + k0_ + ac);\
    uint32_t sB_ = saB + (uint32_t)(stage)*B_STAGE*4;                         \
    cpa16(sB_ + (br*B_PITCH + bc)*4,      Bm + (size_t)(k0_+br)*N + bn + bc); \
    cpa16(sB_ + ((br+8)*B_PITCH + bc)*4,  Bm + (size_t)(k0_+br+8)*N + bn + bc);\
    asm volatile("cp.async.commit_group;");                                   \
}while(0)

    float acc[4][4][4];
#pragma unroll
    for (int i = 0; i < 4; i++)
#pragma unroll
        for (int j = 0; j < 4; j++)
#pragma unroll
            for (int c = 0; c < 4; c++) acc[i][j][c] = 0.f;

    const int T = K >> 4;
    ISSUE_TILE(0, 0);
    ISSUE_TILE(1, 1);

    int buf = 0;
    for (int t = 0; t < T; t++) {
        asm volatile("cp.async.wait_group 1;");
        __syncthreads();
        if (t + 2 < T) ISSUE_TILE((t+2)%3, t+2);

        const uint32_t* Ab = smA + buf*A_STAGE;
        const uint32_t* Bb = smB + buf*B_STAGE;
#pragma unroll
        for (int ks = 0; ks < 2; ks++) {
            const int kk = ks * 8;
            uint32_t af[4][4], bf[4][2];
#pragma unroll
            for (int mt = 0; mt < 4; mt++) {
                int rr = wm*64 + mt*16 + r0;
                int kc = kk + c0;
                af[mt][0] = bits2tf(Ab[rr*A_PITCH + kc]);
                af[mt][1] = bits2tf(Ab[(rr+8)*A_PITCH + kc]);
                af[mt][2] = bits2tf(Ab[rr*A_PITCH + kc + 4]);
                af[mt][3] = bits2tf(Ab[(rr+8)*A_PITCH + kc + 4]);
            }
#pragma unroll
            for (int nt = 0; nt < 4; nt++) {
                int cn = wn*32 + nt*8 + r0;
                int kc = kk + c0;
                bf[nt][0] = bits2tf(Bb[kc*B_PITCH + cn]);
                bf[nt][1] = bits2tf(Bb[(kc+4)*B_PITCH + cn]);
            }
#pragma unroll
            for (int mt = 0; mt < 4; mt++)
#pragma unroll
                for (int nt = 0; nt < 4; nt++)
                    mma8(acc[mt][nt], af[mt], bf[nt][0], bf[nt][1]);
        }
        buf = (buf + 1) % 3;
        __syncthreads();
    }
#undef ISSUE_TILE

    // epilogue
#pragma unroll
    for (int nt = 0; nt < 4; nt++) {
        int n0 = bn + wn*32 + nt*8 + c0*2;
        float bi0 = bias[n0], bi1 = bias[n0 + 1];
#pragma unroll
        for (int mt = 0; mt < 4; mt++) {
            int m0 = bm + wm*64 + mt*16 + r0;
#pragma unroll
            for (int half = 0; half < 2; half++) {
                int m = m0 + half*8;
                float v0 = acc[mt][nt][half*2]     + bi0;
                float v1 = acc[mt][nt][half*2 + 1] + bi1;
                if (GELU) {
                    v0 = 0.5f*v0*(1.0f + erff(v0*0.70710678118654752f));
                    v1 = 0.5f*v1*(1.0f + erff(v1*0.70710678118654752f));
                }
                if (RES) {
                    v0 += res[(size_t)m*N + n0];
                    v1 += res[(size_t)m*N + n0 + 1];
                }
                *(float2*)&C[(size_t)m*N + n0] = make_float2(v0, v1);
            }
        }
    }
}

__global__ __launch_bounds__(256, 2) void mma_gemm_k(
    const float* __restrict__ A, const float* __restrict__ Bm,
    const float* __restrict__ bias, const float* __restrict__ res,
    float* __restrict__ C, int N, int K, int GELU, int RES)
{
    extern __shared__ __align__(16) uint32_t dyn[];
    gemm_body(A, Bm, bias, res, C, N, K, blockIdx.x, blockIdx.y, dyn, GELU, RES);
}

// merged 3-way projection: blockIdx.z selects (A, W, bias, C); N=K=D
struct Proj3 {
    const float *A0, *A1, *A2;
    const float *W0, *W1, *W2;
    const float *b0, *b1, *b2;
    float *C0, *C1, *C2;
};
__global__ __launch_bounds__(256, 2) void mma_gemm3_k(Proj3 p)
{
    extern __shared__ __align__(16) uint32_t dyn[];
    const float *A, *W, *bi; float *C;
    if (blockIdx.z == 0)      { A = p.A0; W = p.W0; bi = p.b0; C = p.C0; }
    else if (blockIdx.z == 1) { A = p.A1; W = p.W1; bi = p.b1; C = p.C1; }
    else                      { A = p.A2; W = p.W2; bi = p.b2; C = p.C2; }
    gemm_body(A, W, bi, nullptr, C, D, D, blockIdx.x, blockIdx.y, dyn, 0, 0);
}

// ---------------- tensor-core flash attention (unchanged) -------------------
#define KS_PITCH 68
#define VS_PITCH 72
#define PS_PITCH 68
#define ATTN_SMEM ((64*KS_PITCH + 64*VS_PITCH + 4*16*PS_PITCH)*4 + 64*4)

__global__ __launch_bounds__(128) void attn_mma_kernel(
    const float* __restrict__ Qb, const float* __restrict__ Kb,
    const float* __restrict__ Vb, const int* __restrict__ ids,
    float* __restrict__ O, int causal)
{
    extern __shared__ __align__(16) uint32_t sm[];
    uint32_t* Ks = sm;
    uint32_t* Vs = Ks + 64*KS_PITCH;
    uint32_t* Ps = Vs + 64*VS_PITCH;
    float* padv  = (float*)(Ps + 4*16*PS_PITCH);

    const int tid  = threadIdx.x;
    const int lane = tid & 31;
    const int warp = tid >> 5;
    const int b  = blockIdx.z, h = blockIdx.y, qt = blockIdx.x;
    const int qbase = qt * 64;
    const int r0 = lane >> 2;
    const int c0 = lane & 3;

    uint32_t qf[8][4];
    {
        const float* Qg = Qb + ((size_t)(b*SS + qbase + warp*16))*D + h*DH;
#pragma unroll
        for (int ks = 0; ks < 8; ks++) {
            int d0 = ks*8 + c0;
            qf[ks][0] = f2tf(Qg[(size_t)r0*D + d0]);
            qf[ks][1] = f2tf(Qg[(size_t)(r0+8)*D + d0]);
            qf[ks][2] = f2tf(Qg[(size_t)r0*D + d0 + 4]);
            qf[ks][3] = f2tf(Qg[(size_t)(r0+8)*D + d0 + 4]);
        }
    }

    float m0 = -3.0e38f, m1 = -3.0e38f, l0 = 0.f, l1 = 0.f;
    float oacc[8][4];
#pragma unroll
    for (int nt = 0; nt < 8; nt++)
#pragma unroll
        for (int c = 0; c < 4; c++) oacc[nt][c] = 0.f;

    const int qlo = qbase + warp*16 + r0;
    uint32_t* Psw = Ps + warp*16*PS_PITCH;
    const int ktend = causal ? qt : (SS/64 - 1);

    for (int kt = 0; kt <= ktend; kt++) {
        const int kbase = kt*64;
        const float* Kg = Kb + ((size_t)(b*SS + kbase))*D + h*DH;
        const float* Vg = Vb + ((size_t)(b*SS + kbase))*D + h*DH;
#pragma unroll
        for (int i = 0; i < 8; i++) {
            int linear = tid + 128*i;
            int row = linear >> 4;
            int col = (linear & 15) * 4;
            float4 kv = *(const float4*)(Kg + (size_t)row*D + col);
            float4 vv = *(const float4*)(Vg + (size_t)row*D + col);
            *(uint4*)&Ks[row*KS_PITCH + col] = make_uint4(f2tf(kv.x),f2tf(kv.y),f2tf(kv.z),f2tf(kv.w));
            *(uint4*)&Vs[row*VS_PITCH + col] = make_uint4(f2tf(vv.x),f2tf(vv.y),f2tf(vv.z),f2tf(vv.w));
        }
        if (tid < 64)
            padv[tid] = (ids[b*SS + kbase + tid] == 0) ? NEGV : 0.f;
        __syncthreads();

        float sacc[8][4];
#pragma unroll
        for (int nt = 0; nt < 8; nt++)
#pragma unroll
            for (int c = 0; c < 4; c++) sacc[nt][c] = 0.f;
#pragma unroll
        for (int ks = 0; ks < 8; ks++) {
            const int kc = ks*8 + c0;
#pragma unroll
            for (int nt = 0; nt < 8; nt++) {
                uint32_t b0 = Ks[(nt*8 + r0)*KS_PITCH + kc];
                uint32_t b1 = Ks[(nt*8 + r0)*KS_PITCH + kc + 4];
                mma8(sacc[nt], qf[ks], b0, b1);
            }
        }

        float tmax0 = -3.0e38f, tmax1 = -3.0e38f;
#pragma unroll
        for (int nt = 0; nt < 8; nt++) {
            int cA = nt*8 + c0*2;
            float pv0 = padv[cA], pv1 = padv[cA+1];
            sacc[nt][0] = sacc[nt][0]*0.125f + pv0;
            sacc[nt][1] = sacc[nt][1]*0.125f + pv1;
            sacc[nt][2] = sacc[nt][2]*0.125f + pv0;
            sacc[nt][3] = sacc[nt][3]*0.125f + pv1;
            if (causal && kt == qt) {
                int g0 = kbase + cA, g1 = g0 + 1;
                if (g0 > qlo)     sacc[nt][0] += NEGV;
                if (g1 > qlo)     sacc[nt][1] += NEGV;
                if (g0 > qlo + 8) sacc[nt][2] += NEGV;
                if (g1 > qlo + 8) sacc[nt][3] += NEGV;
            }
            tmax0 = fmaxf(tmax0, fmaxf(sacc[nt][0], sacc[nt][1]));
            tmax1 = fmaxf(tmax1, fmaxf(sacc[nt][2], sacc[nt][3]));
        }
        tmax0 = fmaxf(tmax0, __shfl_xor_sync(0xffffffffu, tmax0, 1));
        tmax0 = fmaxf(tmax0, __shfl_xor_sync(0xffffffffu, tmax0, 2));
        tmax1 = fmaxf(tmax1, __shfl_xor_sync(0xffffffffu, tmax1, 1));
        tmax1 = fmaxf(tmax1, __shfl_xor_sync(0xffffffffu, tmax1, 2));

        float mn0 = fmaxf(m0, tmax0), mn1 = fmaxf(m1, tmax1);
        float corr0 = __expf(m0 - mn0), corr1 = __expf(m1 - mn1);
        m0 = mn0; m1 = mn1;

        float ts0 = 0.f, ts1 = 0.f;
#pragma unroll
        for (int nt = 0; nt < 8; nt++) {
            float p0 = __expf(sacc[nt][0] - m0);
            float p1 = __expf(sacc[nt][1] - m0);
            float p2 = __expf(sacc[nt][2] - m1);
            float p3 = __expf(sacc[nt][3] - m1);
            ts0 += p0 + p1; ts1 += p2 + p3;
            *(uint2*)&Psw[r0*PS_PITCH + nt*8 + c0*2]     = make_uint2(f2tf(p0), f2tf(p1));
            *(uint2*)&Psw[(r0+8)*PS_PITCH + nt*8 + c0*2] = make_uint2(f2tf(p2), f2tf(p3));
        }
        ts0 += __shfl_xor_sync(0xffffffffu, ts0, 1);
        ts0 += __shfl_xor_sync(0xffffffffu, ts0, 2);
        ts1 += __shfl_xor_sync(0xffffffffu, ts1, 1);
        ts1 += __shfl_xor_sync(0xffffffffu, ts1, 2);
        l0 = l0*corr0 + ts0;
        l1 = l1*corr1 + ts1;

#pragma unroll
        for (int nt = 0; nt < 8; nt++) {
            oacc[nt][0] *= corr0; oacc[nt][1] *= corr0;
            oacc[nt][2] *= corr1; oacc[nt][3] *= corr1;
        }
        __syncwarp();

#pragma unroll
        for (int ks = 0; ks < 8; ks++) {
            const int kc = ks*8 + c0;
            uint32_t af[4];
            af[0] = Psw[r0*PS_PITCH + kc];
            af[1] = Psw[(r0+8)*PS_PITCH + kc];
            af[2] = Psw[r0*PS_PITCH + kc + 4];
            af[3] = Psw[(r0+8)*PS_PITCH + kc + 4];
#pragma unroll
            for (int nt = 0; nt < 8; nt++) {
                uint32_t b0 = Vs[kc*VS_PITCH + nt*8 + r0];
                uint32_t b1 = Vs[(kc + 4)*VS_PITCH + nt*8 + r0];
                mma8(oacc[nt], af, b0, b1);
            }
        }
        __syncthreads();
    }

    float inv0 = 1.f / l0, inv1 = 1.f / l1;
    float* Og = O + ((size_t)(b*SS + qbase + warp*16))*D + h*DH;
#pragma unroll
    for (int nt = 0; nt < 8; nt++) {
        int dcol = nt*8 + c0*2;
        *(float2*)&Og[(size_t)r0*D + dcol] =
            make_float2(oacc[nt][0]*inv0, oacc[nt][1]*inv0);
        *(float2*)&Og[(size_t)(r0+8)*D + dcol] =
            make_float2(oacc[nt][2]*inv1, oacc[nt][3]*inv1);
    }
}

// ---------------- host ----------------
extern "C" void kernel_launch(void* const* d_in, const int* in_sizes, int n_in,
                              void* d_out, int out_size)
{
    const float* emb  = (const float*)d_in[0];
    const int*   iids = (const int*)  d_in[1];
    const int*   tids = (const int*)  d_in[2];
    const float* tok  = (const float*)d_in[3];
    const float* pos  = (const float*)d_in[4];
    const float* ln1g = (const float*)d_in[5];
    const float* ln1b = (const float*)d_in[6];
    const float* q1w  = (const float*)d_in[7];
    const float* q1b  = (const float*)d_in[8];
    const float* k1w  = (const float*)d_in[9];
    const float* k1b  = (const float*)d_in[10];
    const float* v1w  = (const float*)d_in[11];
    const float* v1b  = (const float*)d_in[12];
    const float* o1w  = (const float*)d_in[13];
    const float* o1b  = (const float*)d_in[14];
    const float* ln2g = (const float*)d_in[15];
    const float* ln2b = (const float*)d_in[16];
    const float* q2w  = (const float*)d_in[17];
    const float* q2b  = (const float*)d_in[18];
    const float* k2w  = (const float*)d_in[19];
    const float* k2b  = (const float*)d_in[20];
    const float* v2w  = (const float*)d_in[21];
    const float* v2b  = (const float*)d_in[22];
    const float* o2w  = (const float*)d_in[23];
    const float* o2b  = (const float*)d_in[24];
    const float* ln3g = (const float*)d_in[25];
    const float* ln3b = (const float*)d_in[26];
    const float* w1   = (const float*)d_in[27];
    const float* b1   = (const float*)d_in[28];
    const float* w2   = (const float*)d_in[29];
    const float* b2   = (const float*)d_in[30];
    float* out = (float*)d_out;

    float *xln, *q, *k, *v, *ao, *h, *hln, *r, *z, *mid;
    cudaGetSymbolAddress((void**)&xln, g_xln);
    cudaGetSymbolAddress((void**)&q,   g_q);
    cudaGetSymbolAddress((void**)&k,   g_k);
    cudaGetSymbolAddress((void**)&v,   g_v);
    cudaGetSymbolAddress((void**)&ao,  g_ao);
    cudaGetSymbolAddress((void**)&h,   g_h);
    cudaGetSymbolAddress((void**)&hln, g_hln);
    cudaGetSymbolAddress((void**)&r,   g_r);
    cudaGetSymbolAddress((void**)&z,   g_z);
    cudaGetSymbolAddress((void**)&mid, g_mid);

    cudaFuncSetAttribute(attn_mma_kernel,
                         cudaFuncAttributeMaxDynamicSharedMemorySize, ATTN_SMEM);
    cudaFuncSetAttribute(mma_gemm_k,
                         cudaFuncAttributeMaxDynamicSharedMemorySize, GEMM_SMEM);
    cudaFuncSetAttribute(mma_gemm3_k,
                         cudaFuncAttributeMaxDynamicSharedMemorySize, GEMM_SMEM);

    dim3 gProj(D/128, MTOK/128);        // (8, 32)
    dim3 gProj3(D/128, MTOK/128, 3);    // (8, 32, 3)
    dim3 gMlp1(4*D/128, MTOK/128);      // (32, 32)
    dim3 gAttn(SS/64, NH, BB);          // (32, 16, 2)

    // embedding + LN1
    embed_ln_kernel<<<MTOK, 256>>>(tids, tok, pos, ln1g, ln1b, xln);
    // self-attention q/k/v projections (merged)
    {
        Proj3 p = { xln, xln, xln, q1w, k1w, v1w, q1b, k1b, v1b, q, k, v };
        mma_gemm3_k<<<gProj3, 256, GEMM_SMEM>>>(p);
    }
    // causal self-attention (pad mask over target_ids)
    attn_mma_kernel<<<gAttn, 128, ATTN_SMEM>>>(q, k, v, tids, ao, 1);
    // out-proj + residual
    mma_gemm_k<<<gProj, 256, GEMM_SMEM>>>(ao, o1w, o1b, xln, h, D, D, 0, 1);
    // LN2
    ln_kernel<<<MTOK, 256>>>(h, ln2g, ln2b, hln);
    // cross-attention projections (merged; Q from hln, K/V from encoder)
    {
        Proj3 p = { hln, emb, emb, q2w, k2w, v2w, q2b, k2b, v2b, q, k, v };
        mma_gemm3_k<<<gProj3, 256, GEMM_SMEM>>>(p);
    }
    // cross-attention (pad mask over input_ids)
    attn_mma_kernel<<<gAttn, 128, ATTN_SMEM>>>(q, k, v, iids, ao, 0);
    // out-proj + residual
    mma_gemm_k<<<gProj, 256, GEMM_SMEM>>>(ao, o2w, o2b, hln, r, D, D, 0, 1);
    // LN3
    ln_kernel<<<MTOK, 256>>>(r, ln3g, ln3b, z);
    // MLP
    mma_gemm_k<<<gMlp1, 256, GEMM_SMEM>>>(z, w1, b1, nullptr, mid, 4*D, D, 1, 0);
    mma_gemm_k<<<gProj, 256, GEMM_SMEM>>>(mid, w2, b2, r, out, D, 4*D, 0, 1);
}

// round 13
// speedup vs baseline: 1.1610x; 1.1610x over previous
#include <cuda_runtime.h>
#include <math.h>
#include <stdint.h>

#define D 1024
#define NH 16
#define DH 64
#define BB 2
#define SS 2048
#define MTOK (BB*SS)       // 4096
#define NEGV -1000000000.0f

// ---------------- scratch (device globals; no allocations) ----------------
__device__ float g_xln[MTOK*D];
__device__ float g_q[MTOK*D];
__device__ float g_k[MTOK*D];
__device__ float g_v[MTOK*D];
__device__ float g_ao[MTOK*D];
__device__ float g_h[MTOK*D];
__device__ float g_hln[MTOK*D];
__device__ float g_r[MTOK*D];
__device__ float g_z[MTOK*D];
__device__ float g_mid[(size_t)MTOK*4*D];
__device__ float g_wbuf[16*1024*1024];   // 8x1M proj W, w1 @8M, w2 @12M
__device__ float g_embr[MTOK*D];         // rounded encoder states

__device__ __forceinline__ uint32_t f2tf(float x){
    uint32_t r; asm("cvt.rna.tf32.f32 %0, %1;" : "=r"(r) : "f"(x)); return r;
}
__device__ __forceinline__ float rndtf(float x){ return __uint_as_float(f2tf(x)); }
__device__ __forceinline__ void mma8(float* c, const uint32_t* a, uint32_t b0, uint32_t b1){
    asm volatile(
        "mma.sync.aligned.m16n8k8.row.col.f32.tf32.tf32.f32 "
        "{%0,%1,%2,%3}, {%4,%5,%6,%7}, {%8,%9}, {%0,%1,%2,%3};"
        : "+f"(c[0]), "+f"(c[1]), "+f"(c[2]), "+f"(c[3])
        : "r"(a[0]), "r"(a[1]), "r"(a[2]), "r"(a[3]), "r"(b0), "r"(b1));
}
__device__ __forceinline__ void cpa16(uint32_t s, const void* g){
    asm volatile("cp.async.cg.shared.global [%0], [%1], 16;" :: "r"(s), "l"(g));
}

// ---------------- batched tf32 pre-rounding (weights + encoder) ------------
struct RJobs { const float* s[11]; float* d[11]; int n4[11]; };
__global__ __launch_bounds__(256) void round_k(RJobs j)
{
    int y = blockIdx.y;
    int i = blockIdx.x*256 + threadIdx.x;
    if (i >= j.n4[y]) return;
    float4 v = ((const float4*)j.s[y])[i];
    float4 o = make_float4(rndtf(v.x), rndtf(v.y), rndtf(v.z), rndtf(v.w));
    ((float4*)j.d[y])[i] = o;
}

// ---------------- fused embedding + LayerNorm1 (rounded output) ------------
__global__ __launch_bounds__(256) void embed_ln_kernel(
    const int* __restrict__ tids, const float* __restrict__ tok,
    const float* __restrict__ pos, const float* __restrict__ gam,
    const float* __restrict__ bet, float* __restrict__ out)
{
    int row = blockIdx.x;
    int s   = row % SS;
    int t   = tids[row];
    const float* te = tok + (size_t)t * D;
    const float* pe = pos + (size_t)s * D;
    float v[4];
    float sum = 0.f, sq = 0.f;
#pragma unroll
    for (int i = 0; i < 4; i++) {
        int d = threadIdx.x + 256*i;
        float x = te[d] + pe[d];
        v[i] = x; sum += x; sq += x*x;
    }
    __shared__ float s1[256], s2[256];
    int tid = threadIdx.x;
    s1[tid] = sum; s2[tid] = sq; __syncthreads();
    for (int o = 128; o > 0; o >>= 1) {
        if (tid < o) { s1[tid] += s1[tid+o]; s2[tid] += s2[tid+o]; }
        __syncthreads();
    }
    float mu  = s1[0] * (1.f/D);
    float var = s2[0] * (1.f/D) - mu*mu;
    float rs  = rsqrtf(var + 1e-5f);
#pragma unroll
    for (int i = 0; i < 4; i++) {
        int d = threadIdx.x + 256*i;
        out[(size_t)row*D + d] = rndtf((v[i]-mu)*rs*gam[d] + bet[d]);
    }
}

// ---------------- generic LayerNorm (rounded output) -----------------------
__global__ __launch_bounds__(256) void ln_kernel(
    const float* __restrict__ X, const float* __restrict__ gam,
    const float* __restrict__ bet, float* __restrict__ out)
{
    int row = blockIdx.x;
    const float* x = X + (size_t)row*D;
    float v[4];
    float sum = 0.f, sq = 0.f;
#pragma unroll
    for (int i = 0; i < 4; i++) {
        int d = threadIdx.x + 256*i;
        float xx = x[d];
        v[i] = xx; sum += xx; sq += xx*xx;
    }
    __shared__ float s1[256], s2[256];
    int tid = threadIdx.x;
    s1[tid] = sum; s2[tid] = sq; __syncthreads();
    for (int o = 128; o > 0; o >>= 1) {
        if (tid < o) { s1[tid] += s1[tid+o]; s2[tid] += s2[tid+o]; }
        __syncthreads();
    }
    float mu  = s1[0] * (1.f/D);
    float var = s2[0] * (1.f/D) - mu*mu;
    float rs  = rsqrtf(var + 1e-5f);
#pragma unroll
    for (int i = 0; i < 4; i++) {
        int d = threadIdx.x + 256*i;
        out[(size_t)row*D + d] = rndtf((v[i]-mu)*rs*gam[d] + bet[d]);
    }
}

// ---------------- tf32 GEMM body, 3-stage cp.async, raw fragments ----------
// Inputs MUST be pre-rounded to tf32 grid (truncation in mma is then exact).
#define A_PITCH 20
#define B_PITCH 136
#define A_STAGE (128*A_PITCH)            // 2560 u32
#define B_STAGE (16*B_PITCH)             // 2176 u32
#define GEMM_SMEM ((3*A_STAGE + 3*B_STAGE)*4)   // 56832 B

__device__ __forceinline__ void gemm_body(
    const float* __restrict__ A, const float* __restrict__ Bm,
    const float* __restrict__ bias, const float* __restrict__ res,
    float* __restrict__ C, int N, int K, int bx, int by,
    uint32_t* dyn, int GELU, int RES, int ROUND)
{
    uint32_t* smA = dyn;
    uint32_t* smB = dyn + 3*A_STAGE;

    const int tid  = threadIdx.x;
    const int lane = tid & 31;
    const int warp = tid >> 5;
    const int wm   = warp >> 2;
    const int wn   = warp & 3;
    const int bm   = by * 128;
    const int bn   = bx * 128;
    const int r0   = lane >> 2;
    const int c0   = lane & 3;

    const int ar = tid >> 2,  ac = (tid & 3) * 4;
    const int br = tid >> 5,  bc = (tid & 31) * 4;

    uint32_t saA = (uint32_t)__cvta_generic_to_shared(smA);
    uint32_t saB = (uint32_t)__cvta_generic_to_shared(smB);

#define ISSUE_TILE(stage, t) do{                                              \
    int k0_ = (t) << 4;                                                       \
    uint32_t sA_ = saA + (uint32_t)(stage)*A_STAGE*4;                         \
    cpa16(sA_ + (ar*A_PITCH + ac)*4,      A + (size_t)(bm+ar)*K + k0_ + ac);  \
    cpa16(sA_ + ((ar+64)*A_PITCH + ac)*4, A + (size_t)(bm+ar+64)*K + k0_ + ac);\
    uint32_t sB_ = saB + (uint32_t)(stage)*B_STAGE*4;                         \
    cpa16(sB_ + (br*B_PITCH + bc)*4,      Bm + (size_t)(k0_+br)*N + bn + bc); \
    cpa16(sB_ + ((br+8)*B_PITCH + bc)*4,  Bm + (size_t)(k0_+br+8)*N + bn + bc);\
    asm volatile("cp.async.commit_group;");                                   \
}while(0)

    float acc[4][4][4];
#pragma unroll
    for (int i = 0; i < 4; i++)
#pragma unroll
        for (int j = 0; j < 4; j++)
#pragma unroll
            for (int c = 0; c < 4; c++) acc[i][j][c] = 0.f;

    const int T = K >> 4;
    ISSUE_TILE(0, 0);
    ISSUE_TILE(1, 1);

    int buf = 0;
    for (int t = 0; t < T; t++) {
        // Tail-correct wait: at t==T-1 the LAST committed group is tile T-1
        // itself, so wait_group 1 would allow reading it mid-flight (the R12
        // post-timing divergence). Drain fully on the final iteration.
        if (t < T - 1) asm volatile("cp.async.wait_group 1;");
        else           asm volatile("cp.async.wait_group 0;");
        __syncthreads();              // also protects stage (t+2)%3 == (t-1)%3
        if (t + 2 < T) ISSUE_TILE((t+2)%3, t+2);

        const uint32_t* Ab = smA + buf*A_STAGE;
        const uint32_t* Bb = smB + buf*B_STAGE;
#pragma unroll
        for (int ks = 0; ks < 2; ks++) {
            const int kk = ks * 8;
            uint32_t af[4][4], bf[4][2];
#pragma unroll
            for (int mt = 0; mt < 4; mt++) {
                int rr = wm*64 + mt*16 + r0;
                int kc = kk + c0;
                af[mt][0] = Ab[rr*A_PITCH + kc];
                af[mt][1] = Ab[(rr+8)*A_PITCH + kc];
                af[mt][2] = Ab[rr*A_PITCH + kc + 4];
                af[mt][3] = Ab[(rr+8)*A_PITCH + kc + 4];
            }
#pragma unroll
            for (int nt = 0; nt < 4; nt++) {
                int cn = wn*32 + nt*8 + r0;
                int kc = kk + c0;
                bf[nt][0] = Bb[kc*B_PITCH + cn];
                bf[nt][1] = Bb[(kc+4)*B_PITCH + cn];
            }
#pragma unroll
            for (int mt = 0; mt < 4; mt++)
#pragma unroll
                for (int nt = 0; nt < 4; nt++)
                    mma8(acc[mt][nt], af[mt], bf[nt][0], bf[nt][1]);
        }
        buf = (buf + 1) % 3;
    }
#undef ISSUE_TILE

    // epilogue
#pragma unroll
    for (int nt = 0; nt < 4; nt++) {
        int n0 = bn + wn*32 + nt*8 + c0*2;
        float bi0 = bias[n0], bi1 = bias[n0 + 1];
#pragma unroll
        for (int mt = 0; mt < 4; mt++) {
            int m0 = bm + wm*64 + mt*16 + r0;
#pragma unroll
            for (int half = 0; half < 2; half++) {
                int m = m0 + half*8;
                float v0 = acc[mt][nt][half*2]     + bi0;
                float v1 = acc[mt][nt][half*2 + 1] + bi1;
                if (GELU) {
                    v0 = 0.5f*v0*(1.0f + erff(v0*0.70710678118654752f));
                    v1 = 0.5f*v1*(1.0f + erff(v1*0.70710678118654752f));
                }
                if (RES) {
                    v0 += res[(size_t)m*N + n0];
                    v1 += res[(size_t)m*N + n0 + 1];
                }
                if (ROUND) { v0 = rndtf(v0); v1 = rndtf(v1); }
                *(float2*)&C[(size_t)m*N + n0] = make_float2(v0, v1);
            }
        }
    }
}

__global__ __launch_bounds__(256, 2) void mma_gemm_k(
    const float* __restrict__ A, const float* __restrict__ Bm,
    const float* __restrict__ bias, const float* __restrict__ res,
    float* __restrict__ C, int N, int K, int GELU, int RES, int ROUND)
{
    extern __shared__ __align__(16) uint32_t dyn[];
    gemm_body(A, Bm, bias, res, C, N, K, blockIdx.x, blockIdx.y, dyn, GELU, RES, ROUND);
}

// merged 3-way projection (q/k/v): blockIdx.z selects; outputs rounded
struct Proj3 {
    const float *A0, *A1, *A2;
    const float *W0, *W1, *W2;
    const float *b0, *b1, *b2;
    float *C0, *C1, *C2;
};
__global__ __launch_bounds__(256, 2) void mma_gemm3_k(Proj3 p)
{
    extern __shared__ __align__(16) uint32_t dyn[];
    const float *A, *W, *bi; float *C;
    if (blockIdx.z == 0)      { A = p.A0; W = p.W0; bi = p.b0; C = p.C0; }
    else if (blockIdx.z == 1) { A = p.A1; W = p.W1; bi = p.b1; C = p.C1; }
    else                      { A = p.A2; W = p.W2; bi = p.b2; C = p.C2; }
    gemm_body(A, W, bi, nullptr, C, D, D, blockIdx.x, blockIdx.y, dyn, 0, 0, 1);
}

// ---------------- tensor-core flash attention -------------------------------
// Q/K/V pre-rounded at proj epilogue -> raw bit loads, no cvts except P.
// Output rounded (feeds out-proj A operand).
#define KS_PITCH 68
#define VS_PITCH 72
#define PS_PITCH 68
#define ATTN_SMEM ((64*KS_PITCH + 64*VS_PITCH + 4*16*PS_PITCH)*4 + 64*4)

__global__ __launch_bounds__(128) void attn_mma_kernel(
    const float* __restrict__ Qb, const float* __restrict__ Kb,
    const float* __restrict__ Vb, const int* __restrict__ ids,
    float* __restrict__ O, int causal)
{
    extern __shared__ __align__(16) uint32_t sm[];
    uint32_t* Ks = sm;
    uint32_t* Vs = Ks + 64*KS_PITCH;
    uint32_t* Ps = Vs + 64*VS_PITCH;
    float* padv  = (float*)(Ps + 4*16*PS_PITCH);

    const int tid  = threadIdx.x;
    const int lane = tid & 31;
    const int warp = tid >> 5;
    const int b  = blockIdx.z, h = blockIdx.y, qt = blockIdx.x;
    const int qbase = qt * 64;
    const int r0 = lane >> 2;
    const int c0 = lane & 3;

    uint32_t qf[8][4];
    {
        const uint32_t* Qg = (const uint32_t*)(Qb + ((size_t)(b*SS + qbase + warp*16))*D + h*DH);
#pragma unroll
        for (int ks = 0; ks < 8; ks++) {
            int d0 = ks*8 + c0;
            qf[ks][0] = Qg[(size_t)r0*D + d0];
            qf[ks][1] = Qg[(size_t)(r0+8)*D + d0];
            qf[ks][2] = Qg[(size_t)r0*D + d0 + 4];
            qf[ks][3] = Qg[(size_t)(r0+8)*D + d0 + 4];
        }
    }

    float m0 = -3.0e38f, m1 = -3.0e38f, l0 = 0.f, l1 = 0.f;
    float oacc[8][4];
#pragma unroll
    for (int nt = 0; nt < 8; nt++)
#pragma unroll
        for (int c = 0; c < 4; c++) oacc[nt][c] = 0.f;

    const int qlo = qbase + warp*16 + r0;
    uint32_t* Psw = Ps + warp*16*PS_PITCH;
    const int ktend = causal ? qt : (SS/64 - 1);

    for (int kt = 0; kt <= ktend; kt++) {
        const int kbase = kt*64;
        const uint32_t* Kg = (const uint32_t*)(Kb + ((size_t)(b*SS + kbase))*D + h*DH);
        const uint32_t* Vg = (const uint32_t*)(Vb + ((size_t)(b*SS + kbase))*D + h*DH);
#pragma unroll
        for (int i = 0; i < 8; i++) {
            int linear = tid + 128*i;
            int row = linear >> 4;
            int col = (linear & 15) * 4;
            uint4 kv = *(const uint4*)(Kg + (size_t)row*D + col);
            uint4 vv = *(const uint4*)(Vg + (size_t)row*D + col);
            *(uint4*)&Ks[row*KS_PITCH + col] = kv;
            *(uint4*)&Vs[row*VS_PITCH + col] = vv;
        }
        if (tid < 64)
            padv[tid] = (ids[b*SS + kbase + tid] == 0) ? NEGV : 0.f;
        __syncthreads();

        float sacc[8][4];
#pragma unroll
        for (int nt = 0; nt < 8; nt++)
#pragma unroll
            for (int c = 0; c < 4; c++) sacc[nt][c] = 0.f;
#pragma unroll
        for (int ks = 0; ks < 8; ks++) {
            const int kc = ks*8 + c0;
#pragma unroll
            for (int nt = 0; nt < 8; nt++) {
                uint32_t b0 = Ks[(nt*8 + r0)*KS_PITCH + kc];
                uint32_t b1 = Ks[(nt*8 + r0)*KS_PITCH + kc + 4];
                mma8(sacc[nt], qf[ks], b0, b1);
            }
        }

        float tmax0 = -3.0e38f, tmax1 = -3.0e38f;
#pragma unroll
        for (int nt = 0; nt < 8; nt++) {
            int cA = nt*8 + c0*2;
            float pv0 = padv[cA], pv1 = padv[cA+1];
            sacc[nt][0] = sacc[nt][0]*0.125f + pv0;
            sacc[nt][1] = sacc[nt][1]*0.125f + pv1;
            sacc[nt][2] = sacc[nt][2]*0.125f + pv0;
            sacc[nt][3] = sacc[nt][3]*0.125f + pv1;
            if (causal && kt == qt) {
                int g0 = kbase + cA, g1 = g0 + 1;
                if (g0 > qlo)     sacc[nt][0] += NEGV;
                if (g1 > qlo)     sacc[nt][1] += NEGV;
                if (g0 > qlo + 8) sacc[nt][2] += NEGV;
                if (g1 > qlo + 8) sacc[nt][3] += NEGV;
            }
            tmax0 = fmaxf(tmax0, fmaxf(sacc[nt][0], sacc[nt][1]));
            tmax1 = fmaxf(tmax1, fmaxf(sacc[nt][2], sacc[nt][3]));
        }
        tmax0 = fmaxf(tmax0, __shfl_xor_sync(0xffffffffu, tmax0, 1));
        tmax0 = fmaxf(tmax0, __shfl_xor_sync(0xffffffffu, tmax0, 2));
        tmax1 = fmaxf(tmax1, __shfl_xor_sync(0xffffffffu, tmax1, 1));
        tmax1 = fmaxf(tmax1, __shfl_xor_sync(0xffffffffu, tmax1, 2));

        float mn0 = fmaxf(m0, tmax0), mn1 = fmaxf(m1, tmax1);
        float corr0 = __expf(m0 - mn0), corr1 = __expf(m1 - mn1);
        m0 = mn0; m1 = mn1;

        float ts0 = 0.f, ts1 = 0.f;
#pragma unroll
        for (int nt = 0; nt < 8; nt++) {
            float p0 = __expf(sacc[nt][0] - m0);
            float p1 = __expf(sacc[nt][1] - m0);
            float p2 = __expf(sacc[nt][2] - m1);
            float p3 = __expf(sacc[nt][3] - m1);
            ts0 += p0 + p1; ts1 += p2 + p3;
            *(uint2*)&Psw[r0*PS_PITCH + nt*8 + c0*2]     = make_uint2(f2tf(p0), f2tf(p1));
            *(uint2*)&Psw[(r0+8)*PS_PITCH + nt*8 + c0*2] = make_uint2(f2tf(p2), f2tf(p3));
        }
        ts0 += __shfl_xor_sync(0xffffffffu, ts0, 1);
        ts0 += __shfl_xor_sync(0xffffffffu, ts0, 2);
        ts1 += __shfl_xor_sync(0xffffffffu, ts1, 1);
        ts1 += __shfl_xor_sync(0xffffffffu, ts1, 2);
        l0 = l0*corr0 + ts0;
        l1 = l1*corr1 + ts1;

#pragma unroll
        for (int nt = 0; nt < 8; nt++) {
            oacc[nt][0] *= corr0; oacc[nt][1] *= corr0;
            oacc[nt][2] *= corr1; oacc[nt][3] *= corr1;
        }
        __syncwarp();

#pragma unroll
        for (int ks = 0; ks < 8; ks++) {
            const int kc = ks*8 + c0;
            uint32_t af[4];
            af[0] = Psw[r0*PS_PITCH + kc];
            af[1] = Psw[(r0+8)*PS_PITCH + kc];
            af[2] = Psw[r0*PS_PITCH + kc + 4];
            af[3] = Psw[(r0+8)*PS_PITCH + kc + 4];
#pragma unroll
            for (int nt = 0; nt < 8; nt++) {
                uint32_t b0 = Vs[kc*VS_PITCH + nt*8 + r0];
                uint32_t b1 = Vs[(kc + 4)*VS_PITCH + nt*8 + r0];
                mma8(oacc[nt], af, b0, b1);
            }
        }
        __syncthreads();
    }

    float inv0 = 1.f / l0, inv1 = 1.f / l1;
    float* Og = O + ((size_t)(b*SS + qbase + warp*16))*D + h*DH;
#pragma unroll
    for (int nt = 0; nt < 8; nt++) {
        int dcol = nt*8 + c0*2;
        *(float2*)&Og[(size_t)r0*D + dcol] =
            make_float2(rndtf(oacc[nt][0]*inv0), rndtf(oacc[nt][1]*inv0));
        *(float2*)&Og[(size_t)(r0+8)*D + dcol] =
            make_float2(rndtf(oacc[nt][2]*inv1), rndtf(oacc[nt][3]*inv1));
    }
}

// ---------------- host ----------------
extern "C" void kernel_launch(void* const* d_in, const int* in_sizes, int n_in,
                              void* d_out, int out_size)
{
    const float* emb  = (const float*)d_in[0];
    const int*   iids = (const int*)  d_in[1];
    const int*   tids = (const int*)  d_in[2];
    const float* tok  = (const float*)d_in[3];
    const float* pos  = (const float*)d_in[4];
    const float* ln1g = (const float*)d_in[5];
    const float* ln1b = (const float*)d_in[6];
    const float* q1w  = (const float*)d_in[7];
    const float* q1b  = (const float*)d_in[8];
    const float* k1w  = (const float*)d_in[9];
    const float* k1b  = (const float*)d_in[10];
    const float* v1w  = (const float*)d_in[11];
    const float* v1b  = (const float*)d_in[12];
    const float* o1w  = (const float*)d_in[13];
    const float* o1b  = (const float*)d_in[14];
    const float* ln2g = (const float*)d_in[15];
    const float* ln2b = (const float*)d_in[16];
    const float* q2w  = (const float*)d_in[17];
    const float* q2b  = (const float*)d_in[18];
    const float* k2w  = (const float*)d_in[19];
    const float* k2b  = (const float*)d_in[20];
    const float* v2w  = (const float*)d_in[21];
    const float* v2b  = (const float*)d_in[22];
    const float* o2w  = (const float*)d_in[23];
    const float* o2b  = (const float*)d_in[24];
    const float* ln3g = (const float*)d_in[25];
    const float* ln3b = (const float*)d_in[26];
    const float* w1   = (const float*)d_in[27];
    const float* b1   = (const float*)d_in[28];
    const float* w2   = (const float*)d_in[29];
    const float* b2   = (const float*)d_in[30];
    float* out = (float*)d_out;

    float *xln, *q, *k, *v, *ao, *h, *hln, *r, *z, *mid, *wbuf, *embr;
    cudaGetSymbolAddress((void**)&xln,  g_xln);
    cudaGetSymbolAddress((void**)&q,    g_q);
    cudaGetSymbolAddress((void**)&k,    g_k);
    cudaGetSymbolAddress((void**)&v,    g_v);
    cudaGetSymbolAddress((void**)&ao,   g_ao);
    cudaGetSymbolAddress((void**)&h,    g_h);
    cudaGetSymbolAddress((void**)&hln,  g_hln);
    cudaGetSymbolAddress((void**)&r,    g_r);
    cudaGetSymbolAddress((void**)&z,    g_z);
    cudaGetSymbolAddress((void**)&mid,  g_mid);
    cudaGetSymbolAddress((void**)&wbuf, g_wbuf);
    cudaGetSymbolAddress((void**)&embr, g_embr);

    const int M1 = 1024*1024;
    float* rq1 = wbuf + 0*M1;  float* rk1 = wbuf + 1*M1;
    float* rv1 = wbuf + 2*M1;  float* ro1 = wbuf + 3*M1;
    float* rq2 = wbuf + 4*M1;  float* rk2 = wbuf + 5*M1;
    float* rv2 = wbuf + 6*M1;  float* ro2 = wbuf + 7*M1;
    float* rw1 = wbuf + 8*M1;  float* rw2 = wbuf + 12*M1;

    cudaFuncSetAttribute(attn_mma_kernel,
                         cudaFuncAttributeMaxDynamicSharedMemorySize, ATTN_SMEM);
    cudaFuncSetAttribute(mma_gemm_k,
                         cudaFuncAttributeMaxDynamicSharedMemorySize, GEMM_SMEM);
    cudaFuncSetAttribute(mma_gemm3_k,
                         cudaFuncAttributeMaxDynamicSharedMemorySize, GEMM_SMEM);

    dim3 gProj(D/128, MTOK/128);        // (8, 32)
    dim3 gProj3(D/128, MTOK/128, 3);    // (8, 32, 3)
    dim3 gMlp1(4*D/128, MTOK/128);      // (32, 32)
    dim3 gAttn(SS/64, NH, BB);          // (32, 16, 2)

    // pre-round weights + encoder states to tf32 grid
    {
        RJobs j;
        const float* srcs[11] = { q1w, k1w, v1w, o1w, q2w, k2w, v2w, o2w, w1, w2, emb };
        float*       dsts[11] = { rq1, rk1, rv1, ro1, rq2, rk2, rv2, ro2, rw1, rw2, embr };
        int          n4s [11] = { M1/4, M1/4, M1/4, M1/4, M1/4, M1/4, M1/4, M1/4,
                                  M1, M1, M1 };   // 4M elems -> 1M float4
        for (int i = 0; i < 11; i++) { j.s[i] = srcs[i]; j.d[i] = dsts[i]; j.n4[i] = n4s[i]; }
        round_k<<<dim3(4096, 11), 256>>>(j);
    }
    // embedding + LN1 (rounded)
    embed_ln_kernel<<<MTOK, 256>>>(tids, tok, pos, ln1g, ln1b, xln);
    // self-attention q/k/v projections (merged, rounded out)
    {
        Proj3 p = { xln, xln, xln, rq1, rk1, rv1, q1b, k1b, v1b, q, k, v };
        mma_gemm3_k<<<gProj3, 256, GEMM_SMEM>>>(p);
    }
    // causal self-attention (pad mask over target_ids)
    attn_mma_kernel<<<gAttn, 128, ATTN_SMEM>>>(q, k, v, tids, ao, 1);
    // out-proj + residual
    mma_gemm_k<<<gProj, 256, GEMM_SMEM>>>(ao, ro1, o1b, xln, h, D, D, 0, 1, 0);
    // LN2 (rounded)
    ln_kernel<<<MTOK, 256>>>(h, ln2g, ln2b, hln);
    // cross-attention projections (merged; Q from hln, K/V from encoder)
    {
        Proj3 p = { hln, embr, embr, rq2, rk2, rv2, q2b, k2b, v2b, q, k, v };
        mma_gemm3_k<<<gProj3, 256, GEMM_SMEM>>>(p);
    }
    // cross-attention (pad mask over input_ids)
    attn_mma_kernel<<<gAttn, 128, ATTN_SMEM>>>(q, k, v, iids, ao, 0);
    // out-proj + residual
    mma_gemm_k<<<gProj, 256, GEMM_SMEM>>>(ao, ro2, o2b, hln, r, D, D, 0, 1, 0);
    // LN3 (rounded)
    ln_kernel<<<MTOK, 256>>>(r, ln3g, ln3b, z);
    // MLP: mid rounded (feeds GEMM2 A), final out unrounded
    mma_gemm_k<<<gMlp1, 256, GEMM_SMEM>>>(z, rw1, b1, nullptr, mid, 4*D, D, 1, 0, 1);
    mma_gemm_k<<<gProj, 256, GEMM_SMEM>>>(mid, rw2, b2, r, out, D, 4*D, 0, 1, 0);
}